// round 8
// baseline (speedup 1.0000x reference)
#include <cuda_runtime.h>
#include <cuda_bf16.h>
#include <cuda_fp16.h>
#include <cstdint>

#define NTOK   (8 * 2048)
#define EDIM   512
#define NHEAD  64
#define DK     8

typedef unsigned long long u64;

// Z: single fp16 (|Z|<=1, quant err 2^-11). W: split fp16 (hi + lo).
__device__ __half g_Zf[NTOK * EDIM];
__device__ __half g_Wh[EDIM * EDIM];
__device__ __half g_Wl[EDIM * EDIM];

__device__ __forceinline__ uint32_t smem_to_u32(const void* p) {
    uint32_t a;
    asm("{ .reg .u64 t; cvta.to.shared.u64 t, %1; cvt.u32.u64 %0, t; }" : "=r"(a) : "l"(p));
    return a;
}

// Packed fp32x2 math (Blackwell)
__device__ __forceinline__ void fma2(u64 &d, u64 a, u64 b) {
    asm("fma.rn.f32x2 %0, %1, %2, %3;" : "=l"(d) : "l"(a), "l"(b), "l"(d));
}
__device__ __forceinline__ void add2(u64 &d, u64 a) {
    asm("add.rn.f32x2 %0, %1, %2;" : "=l"(d) : "l"(d), "l"(a));
}
__device__ __forceinline__ u64 pack2(float lo, float hi) {
    u64 r; asm("mov.b64 %0, {%1, %2};" : "=l"(r) : "f"(lo), "f"(hi)); return r;
}
__device__ __forceinline__ float2 unpack2(u64 v) {
    float2 r; asm("mov.b64 {%0, %1}, %2;" : "=f"(r.x), "=f"(r.y) : "l"(v)); return r;
}
__device__ __forceinline__ float ex2(float x) {
    float r; asm("ex2.approx.ftz.f32 %0, %1;" : "=f"(r) : "f"(x)); return r;
}

// Baseline-PTX tensor path (sm_80+)
#define CP16(dst, src) \
    asm volatile("cp.async.cg.shared.global [%0], [%1], 16;" :: "r"(dst), "l"(src))
#define CP_COMMIT()  asm volatile("cp.async.commit_group;" ::: "memory")
#define CP_WAIT1()   asm volatile("cp.async.wait_group 1;" ::: "memory")
#define CP_WAIT0()   asm volatile("cp.async.wait_group 0;" ::: "memory")

#define LDSM4(r, addr) \
    asm volatile("ldmatrix.sync.aligned.m8n8.x4.shared.b16 {%0,%1,%2,%3}, [%4];" \
        : "=r"((r)[0]), "=r"((r)[1]), "=r"((r)[2]), "=r"((r)[3]) : "r"(addr))

#define MMA_F16(d, a, b) \
    asm volatile("mma.sync.aligned.m16n8k16.row.col.f32.f16.f16.f32 " \
        "{%0,%1,%2,%3}, {%4,%5,%6,%7}, {%8,%9}, {%0,%1,%2,%3};" \
        : "+f"((d)[0]), "+f"((d)[1]), "+f"((d)[2]), "+f"((d)[3]) \
        : "r"((a)[0]), "r"((a)[1]), "r"((a)[2]), "r"((a)[3]), "r"((b)[0]), "r"((b)[1]))

// ---------------------------------------------------------------------------
// Kernel A: blocks [0, QBLOCKS): projection + head-axis attention (warp/token)
//           blocks [QBLOCKS, ...): W hi/lo fp16 split (merged launch)
// ---------------------------------------------------------------------------
#define QBLOCKS (NTOK / 8)

__global__ __launch_bounds__(256) void qattn_kernel(const float* __restrict__ x,
                                                    const float* __restrict__ theta,
                                                    const float* __restrict__ W) {
    const int tid = threadIdx.x;

    if (blockIdx.x >= QBLOCKS) {   // -------- W split branch --------
        int i = (blockIdx.x - QBLOCKS) * 256 + tid;
        float w = W[i];
        __half h = __float2half_rn(w);
        g_Wh[i] = h;
        g_Wl[i] = __float2half_rn(w - __half2float(h));
        return;
    }

    __shared__ float Psm[8][NHEAD][DK];
    __shared__ float th[DK];
    if (tid < DK) th[tid] = theta[tid];
    __syncthreads();

    const int w = tid >> 5, lane = tid & 31;
    const int token = blockIdx.x * 8 + w;
    const float* xr = x + (size_t)token * EDIM;

    float pa[8], pb[8];
    {
        float4 v0 = *(const float4*)(xr + lane * 8);
        float4 v1 = *(const float4*)(xr + lane * 8 + 4);
        pa[0] = __cosf(v0.x + th[0]); pa[1] = __cosf(v0.y + th[1]);
        pa[2] = __cosf(v0.z + th[2]); pa[3] = __cosf(v0.w + th[3]);
        pa[4] = __cosf(v1.x + th[4]); pa[5] = __cosf(v1.y + th[5]);
        pa[6] = __cosf(v1.z + th[6]); pa[7] = __cosf(v1.w + th[7]);
        float4 u0 = *(const float4*)(xr + (lane + 32) * 8);
        float4 u1 = *(const float4*)(xr + (lane + 32) * 8 + 4);
        pb[0] = __cosf(u0.x + th[0]); pb[1] = __cosf(u0.y + th[1]);
        pb[2] = __cosf(u0.z + th[2]); pb[3] = __cosf(u0.w + th[3]);
        pb[4] = __cosf(u1.x + th[4]); pb[5] = __cosf(u1.y + th[5]);
        pb[6] = __cosf(u1.z + th[6]); pb[7] = __cosf(u1.w + th[7]);
    }

    float* Pw = &Psm[w][0][0];
    *(float4*)(Pw + lane * 8)            = make_float4(pa[0], pa[1], pa[2], pa[3]);
    *(float4*)(Pw + lane * 8 + 4)        = make_float4(pa[4], pa[5], pa[6], pa[7]);
    *(float4*)(Pw + (lane + 32) * 8)     = make_float4(pb[0], pb[1], pb[2], pb[3]);
    *(float4*)(Pw + (lane + 32) * 8 + 4) = make_float4(pb[4], pb[5], pb[6], pb[7]);
    __syncwarp();

    const float inv = 0.35355339059327373f * 1.4426950408889634f;  // /sqrt(8)/ln2
    u64 uqa[4], uqb[4];
#pragma unroll
    for (int i = 0; i < 4; i++) {
        uqa[i] = pack2(pa[2*i] * inv, pa[2*i+1] * inv);
        uqb[i] = pack2(pb[2*i] * inv, pb[2*i+1] * inv);
    }

    u64 sum2 = 0ull, uoa[4], uob[4];
#pragma unroll
    for (int i = 0; i < 4; i++) { uoa[i] = 0ull; uob[i] = 0ull; }

    const ulonglong2* Pw2 = (const ulonglong2*)Pw;
#pragma unroll 8
    for (int g = 0; g < NHEAD; g++) {
        ulonglong2 p0 = Pw2[g * 2];
        ulonglong2 p1 = Pw2[g * 2 + 1];
        u64 ta = 0ull, tb = 0ull;
        fma2(ta, uqa[0], p0.x); fma2(ta, uqa[1], p0.y);
        fma2(ta, uqa[2], p1.x); fma2(ta, uqa[3], p1.y);
        fma2(tb, uqb[0], p0.x); fma2(tb, uqb[1], p0.y);
        fma2(tb, uqb[2], p1.x); fma2(tb, uqb[3], p1.y);
        float2 va = unpack2(ta), vb = unpack2(tb);
        float wa = ex2(va.x + va.y);
        float wb = ex2(vb.x + vb.y);
        add2(sum2, pack2(wa, wb));
        u64 waa = pack2(wa, wa), wbb = pack2(wb, wb);
        fma2(uoa[0], p0.x, waa); fma2(uoa[1], p0.y, waa);
        fma2(uoa[2], p1.x, waa); fma2(uoa[3], p1.y, waa);
        fma2(uob[0], p0.x, wbb); fma2(uob[1], p0.y, wbb);
        fma2(uob[2], p1.x, wbb); fma2(uob[3], p1.y, wbb);
    }

    float2 sums = unpack2(sum2);
    const float ra = 1.0f / sums.x, rb = 1.0f / sums.y;
    const int b = token >> 11, s = token & 2047;
    const size_t idxA = ((size_t)b << 20) + ((size_t)lane << 14) + s * 8;
    const size_t idxB = ((size_t)b << 20) + ((size_t)(lane + 32) << 14) + s * 8;

    union { __half e[8]; uint4 v; } uf;
#pragma unroll
    for (int i = 0; i < 4; i++) {
        float2 v = unpack2(uoa[i]);
        uf.e[2*i]   = __float2half_rn(v.x * ra);
        uf.e[2*i+1] = __float2half_rn(v.y * ra);
    }
    *(uint4*)(g_Zf + idxA) = uf.v;
#pragma unroll
    for (int i = 0; i < 4; i++) {
        float2 v = unpack2(uob[i]);
        uf.e[2*i]   = __float2half_rn(v.x * rb);
        uf.e[2*i+1] = __float2half_rn(v.y * rb);
    }
    *(uint4*)(g_Zf + idxB) = uf.v;
}

// ---------------------------------------------------------------------------
// Kernel B: HMMA GEMM  Y[16384,512] = Z @ W^T + bias
// fp16 2-product: acc = Z*Wh + Z*Wl  (fp32 accumulate).
// CTA 128x128, 8 warps x (64x32), K chunks of 32.
// 3-stage cp.async pipeline, ONE __syncthreads per chunk (2-chunk lookahead
// covers DRAM latency; stage written at iter c is the one consumed at c-1,
// already drained by the barrier).
// ---------------------------------------------------------------------------
#define RSTRIDE 80
#define ARR     (128 * RSTRIDE)     // 10240 B
#define O_Z     0
#define O_WH    (1 * ARR)
#define O_WL    (2 * ARR)
#define STAGE   (3 * ARR)           // 30720 B
#define NSTAGE  3
#define NCHUNK  (EDIM / 32)         // 16
#define SMEM_TOTAL (NSTAGE * STAGE) // 92160 B

__global__ __launch_bounds__(256, 2) void gemm_kernel(const float* __restrict__ bias,
                                                      float* __restrict__ Y) {
    extern __shared__ char smem[];
    const uint32_t smem_base = smem_to_u32(smem);
    const int tid = threadIdx.x, wid = tid >> 5, lane = tid & 31;
    const int bx = blockIdx.x, by = blockIdx.y;

    const int row = tid >> 1, half = tid & 1;
    const size_t zbase = (size_t)(by * 128 + row) * EDIM + half * 16;
    const size_t wbase = (size_t)(bx * 128 + row) * EDIM + half * 16;
    const uint32_t sdst = smem_base + row * RSTRIDE + half * 32;

    const int wm = wid & 1, wn = wid >> 1;

    const int la_row = lane & 15;
    const int la_kh  = (lane >> 4) & 1;
    const int lb_n   = (lane & 7) + ((lane & 16) >> 1);
    const int lb_kh  = (lane >> 3) & 1;

    float acc[4][4][4];
#pragma unroll
    for (int i = 0; i < 4; i++)
#pragma unroll
        for (int j = 0; j < 4; j++)
#pragma unroll
            for (int k = 0; k < 4; k++) acc[i][j][k] = 0.f;

#define ISSUE(c, st) do { \
    uint32_t d = sdst + (st) * STAGE; \
    size_t  zo = zbase + (size_t)(c) * 32; \
    size_t  wo = wbase + (size_t)(c) * 32; \
    CP16(d + O_Z,       (const char*)(g_Zf + zo)); \
    CP16(d + O_Z  + 16, (const char*)(g_Zf + zo + 8)); \
    CP16(d + O_WH,      (const char*)(g_Wh + wo)); \
    CP16(d + O_WH + 16, (const char*)(g_Wh + wo + 8)); \
    CP16(d + O_WL,      (const char*)(g_Wl + wo)); \
    CP16(d + O_WL + 16, (const char*)(g_Wl + wo + 8)); \
} while (0)

    ISSUE(0, 0); CP_COMMIT();
    ISSUE(1, 1); CP_COMMIT();

    int st = 0;
    for (int c = 0; c < NCHUNK; c++) {
        if (c < NCHUNK - 1) CP_WAIT1();   // chunk c landed, c+1 in flight
        else                CP_WAIT0();   // tail: only chunk c in flight
        __syncthreads();

        if (c + 2 < NCHUNK) {             // refill stage of chunk c-1 (drained)
            int wst = st + 2; if (wst >= NSTAGE) wst -= NSTAGE;
            ISSUE(c + 2, wst);
            CP_COMMIT();
        }

        const uint32_t sg = smem_base + st * STAGE;
        const uint32_t aZ  = sg + O_Z  + (wm * 64 + la_row) * RSTRIDE + la_kh * 16;
        const uint32_t bWH = sg + O_WH + (wn * 32 + lb_n) * RSTRIDE + lb_kh * 16;
        const uint32_t bWL = sg + O_WL + (wn * 32 + lb_n) * RSTRIDE + lb_kh * 16;

#pragma unroll
        for (int ks = 0; ks < 2; ks++) {
            const uint32_t ko = ks * 32;
            uint32_t bh[4][2], bl[4][2];
#pragma unroll
            for (int np = 0; np < 2; np++) {
                uint32_t t[4];
                LDSM4(t, bWH + np * 16 * RSTRIDE + ko);
                bh[2*np][0] = t[0]; bh[2*np][1] = t[1];
                bh[2*np+1][0] = t[2]; bh[2*np+1][1] = t[3];
                LDSM4(t, bWL + np * 16 * RSTRIDE + ko);
                bl[2*np][0] = t[0]; bl[2*np][1] = t[1];
                bl[2*np+1][0] = t[2]; bl[2*np+1][1] = t[3];
            }
#pragma unroll
            for (int mp = 0; mp < 2; mp++) {
                uint32_t az[2][4];
                LDSM4(az[0], aZ + (mp * 2 + 0) * 16 * RSTRIDE + ko);
                LDSM4(az[1], aZ + (mp * 2 + 1) * 16 * RSTRIDE + ko);
#pragma unroll
                for (int m2 = 0; m2 < 2; m2++)
#pragma unroll
                    for (int nt = 0; nt < 4; nt++)
                        MMA_F16(acc[mp*2+m2][nt], az[m2], bh[nt]);
#pragma unroll
                for (int m2 = 0; m2 < 2; m2++)
#pragma unroll
                    for (int nt = 0; nt < 4; nt++)
                        MMA_F16(acc[mp*2+m2][nt], az[m2], bl[nt]);
            }
        }

        if (++st == NSTAGE) st = 0;
    }

    const int g = lane >> 2, cq = 2 * (lane & 3);
#pragma unroll
    for (int nt = 0; nt < 4; nt++) {
        const int col = bx * 128 + wn * 32 + nt * 8 + cq;
        const float2 bv = *(const float2*)(bias + col);
#pragma unroll
        for (int mt = 0; mt < 4; mt++) {
            const int r0 = by * 128 + wm * 64 + mt * 16 + g;
            float2 v0 = make_float2(acc[mt][nt][0] + bv.x, acc[mt][nt][1] + bv.y);
            float2 v1 = make_float2(acc[mt][nt][2] + bv.x, acc[mt][nt][3] + bv.y);
            *(float2*)(Y + (size_t)r0 * EDIM + col)       = v0;
            *(float2*)(Y + (size_t)(r0 + 8) * EDIM + col) = v1;
        }
    }
}

// ---------------------------------------------------------------------------
extern "C" void kernel_launch(void* const* d_in, const int* in_sizes, int n_in,
                              void* d_out, int out_size) {
    const float* x     = (const float*)d_in[0];
    const float* theta = (const float*)d_in[1];
    const float* W     = (const float*)d_in[2];
    const float* bias  = (const float*)d_in[3];
    float* out = (float*)d_out;

    cudaFuncSetAttribute(gemm_kernel, cudaFuncAttributeMaxDynamicSharedMemorySize, SMEM_TOTAL);

    qattn_kernel<<<QBLOCKS + EDIM * EDIM / 256, 256>>>(x, theta, W);
    gemm_kernel<<<dim3(EDIM / 128, NTOK / 128), 256, SMEM_TOTAL>>>(bias, out);
}

// round 9
// speedup vs baseline: 1.2579x; 1.2579x over previous
#include <cuda_runtime.h>
#include <cuda_bf16.h>
#include <cuda_fp16.h>
#include <cstdint>

#define NTOK   (8 * 2048)
#define EDIM   512
#define NHEAD  64
#define DK     8

typedef unsigned long long u64;

// Single-fp16 operands: Z (|Z|<=1) and W, both quantized ~2^-12 rms rel.
__device__ __half g_Zf[NTOK * EDIM];
__device__ __half g_Wf[EDIM * EDIM];

__device__ __forceinline__ uint32_t smem_to_u32(const void* p) {
    uint32_t a;
    asm("{ .reg .u64 t; cvta.to.shared.u64 t, %1; cvt.u32.u64 %0, t; }" : "=r"(a) : "l"(p));
    return a;
}

// Packed fp32x2 math (Blackwell)
__device__ __forceinline__ void fma2(u64 &d, u64 a, u64 b) {
    asm("fma.rn.f32x2 %0, %1, %2, %3;" : "=l"(d) : "l"(a), "l"(b), "l"(d));
}
__device__ __forceinline__ void add2(u64 &d, u64 a) {
    asm("add.rn.f32x2 %0, %1, %2;" : "=l"(d) : "l"(d), "l"(a));
}
__device__ __forceinline__ u64 pack2(float lo, float hi) {
    u64 r; asm("mov.b64 %0, {%1, %2};" : "=l"(r) : "f"(lo), "f"(hi)); return r;
}
__device__ __forceinline__ float2 unpack2(u64 v) {
    float2 r; asm("mov.b64 {%0, %1}, %2;" : "=f"(r.x), "=f"(r.y) : "l"(v)); return r;
}
__device__ __forceinline__ float ex2(float x) {
    float r; asm("ex2.approx.ftz.f32 %0, %1;" : "=f"(r) : "f"(x)); return r;
}

// Baseline-PTX tensor path (sm_80+)
#define CP16(dst, src) \
    asm volatile("cp.async.cg.shared.global [%0], [%1], 16;" :: "r"(dst), "l"(src))
#define CP_COMMIT()  asm volatile("cp.async.commit_group;" ::: "memory")
#define CP_WAIT1()   asm volatile("cp.async.wait_group 1;" ::: "memory")
#define CP_WAIT0()   asm volatile("cp.async.wait_group 0;" ::: "memory")

#define LDSM4(r, addr) \
    asm volatile("ldmatrix.sync.aligned.m8n8.x4.shared.b16 {%0,%1,%2,%3}, [%4];" \
        : "=r"((r)[0]), "=r"((r)[1]), "=r"((r)[2]), "=r"((r)[3]) : "r"(addr))

#define MMA_F16(d, a, b) \
    asm volatile("mma.sync.aligned.m16n8k16.row.col.f32.f16.f16.f32 " \
        "{%0,%1,%2,%3}, {%4,%5,%6,%7}, {%8,%9}, {%0,%1,%2,%3};" \
        : "+f"((d)[0]), "+f"((d)[1]), "+f"((d)[2]), "+f"((d)[3]) \
        : "r"((a)[0]), "r"((a)[1]), "r"((a)[2]), "r"((a)[3]), "r"((b)[0]), "r"((b)[1]))

// ---------------------------------------------------------------------------
// Kernel A: blocks [0, QBLOCKS): projection + head-axis attention (warp/token)
//           blocks [QBLOCKS, ...): W fp16 quantize (merged launch)
// ---------------------------------------------------------------------------
#define QBLOCKS (NTOK / 8)

__global__ __launch_bounds__(256) void qattn_kernel(const float* __restrict__ x,
                                                    const float* __restrict__ theta,
                                                    const float* __restrict__ W) {
    const int tid = threadIdx.x;

    if (blockIdx.x >= QBLOCKS) {   // -------- W quantize branch --------
        int i = (blockIdx.x - QBLOCKS) * 256 + tid;
        g_Wf[i] = __float2half_rn(W[i]);
        return;
    }

    __shared__ float Psm[8][NHEAD][DK];
    __shared__ float th[DK];
    if (tid < DK) th[tid] = theta[tid];
    __syncthreads();

    const int w = tid >> 5, lane = tid & 31;
    const int token = blockIdx.x * 8 + w;
    const float* xr = x + (size_t)token * EDIM;

    float pa[8], pb[8];
    {
        float4 v0 = *(const float4*)(xr + lane * 8);
        float4 v1 = *(const float4*)(xr + lane * 8 + 4);
        pa[0] = __cosf(v0.x + th[0]); pa[1] = __cosf(v0.y + th[1]);
        pa[2] = __cosf(v0.z + th[2]); pa[3] = __cosf(v0.w + th[3]);
        pa[4] = __cosf(v1.x + th[4]); pa[5] = __cosf(v1.y + th[5]);
        pa[6] = __cosf(v1.z + th[6]); pa[7] = __cosf(v1.w + th[7]);
        float4 u0 = *(const float4*)(xr + (lane + 32) * 8);
        float4 u1 = *(const float4*)(xr + (lane + 32) * 8 + 4);
        pb[0] = __cosf(u0.x + th[0]); pb[1] = __cosf(u0.y + th[1]);
        pb[2] = __cosf(u0.z + th[2]); pb[3] = __cosf(u0.w + th[3]);
        pb[4] = __cosf(u1.x + th[4]); pb[5] = __cosf(u1.y + th[5]);
        pb[6] = __cosf(u1.z + th[6]); pb[7] = __cosf(u1.w + th[7]);
    }

    float* Pw = &Psm[w][0][0];
    *(float4*)(Pw + lane * 8)            = make_float4(pa[0], pa[1], pa[2], pa[3]);
    *(float4*)(Pw + lane * 8 + 4)        = make_float4(pa[4], pa[5], pa[6], pa[7]);
    *(float4*)(Pw + (lane + 32) * 8)     = make_float4(pb[0], pb[1], pb[2], pb[3]);
    *(float4*)(Pw + (lane + 32) * 8 + 4) = make_float4(pb[4], pb[5], pb[6], pb[7]);
    __syncwarp();

    const float inv = 0.35355339059327373f * 1.4426950408889634f;  // /sqrt(8)/ln2
    u64 uqa[4], uqb[4];
#pragma unroll
    for (int i = 0; i < 4; i++) {
        uqa[i] = pack2(pa[2*i] * inv, pa[2*i+1] * inv);
        uqb[i] = pack2(pb[2*i] * inv, pb[2*i+1] * inv);
    }

    u64 sum2 = 0ull, uoa[4], uob[4];
#pragma unroll
    for (int i = 0; i < 4; i++) { uoa[i] = 0ull; uob[i] = 0ull; }

    const ulonglong2* Pw2 = (const ulonglong2*)Pw;
#pragma unroll 8
    for (int g = 0; g < NHEAD; g++) {
        ulonglong2 p0 = Pw2[g * 2];
        ulonglong2 p1 = Pw2[g * 2 + 1];
        u64 ta = 0ull, tb = 0ull;
        fma2(ta, uqa[0], p0.x); fma2(ta, uqa[1], p0.y);
        fma2(ta, uqa[2], p1.x); fma2(ta, uqa[3], p1.y);
        fma2(tb, uqb[0], p0.x); fma2(tb, uqb[1], p0.y);
        fma2(tb, uqb[2], p1.x); fma2(tb, uqb[3], p1.y);
        float2 va = unpack2(ta), vb = unpack2(tb);
        float wa = ex2(va.x + va.y);
        float wb = ex2(vb.x + vb.y);
        add2(sum2, pack2(wa, wb));
        u64 waa = pack2(wa, wa), wbb = pack2(wb, wb);
        fma2(uoa[0], p0.x, waa); fma2(uoa[1], p0.y, waa);
        fma2(uoa[2], p1.x, waa); fma2(uoa[3], p1.y, waa);
        fma2(uob[0], p0.x, wbb); fma2(uob[1], p0.y, wbb);
        fma2(uob[2], p1.x, wbb); fma2(uob[3], p1.y, wbb);
    }

    float2 sums = unpack2(sum2);
    const float ra = 1.0f / sums.x, rb = 1.0f / sums.y;
    const int b = token >> 11, s = token & 2047;
    const size_t idxA = ((size_t)b << 20) + ((size_t)lane << 14) + s * 8;
    const size_t idxB = ((size_t)b << 20) + ((size_t)(lane + 32) << 14) + s * 8;

    union { __half e[8]; uint4 v; } uf;
#pragma unroll
    for (int i = 0; i < 4; i++) {
        float2 v = unpack2(uoa[i]);
        uf.e[2*i]   = __float2half_rn(v.x * ra);
        uf.e[2*i+1] = __float2half_rn(v.y * ra);
    }
    *(uint4*)(g_Zf + idxA) = uf.v;
#pragma unroll
    for (int i = 0; i < 4; i++) {
        float2 v = unpack2(uob[i]);
        uf.e[2*i]   = __float2half_rn(v.x * rb);
        uf.e[2*i+1] = __float2half_rn(v.y * rb);
    }
    *(uint4*)(g_Zf + idxB) = uf.v;
}

// ---------------------------------------------------------------------------
// Kernel B: HMMA GEMM  Y[16384,512] = Z @ W^T + bias
// Single fp16 product, fp32 accumulate. CTA 128x128, 8 warps x (64x32),
// K chunks of 32, 3-stage cp.async pipeline, one __syncthreads per chunk.
// ---------------------------------------------------------------------------
#define RSTRIDE 80
#define ARR     (128 * RSTRIDE)     // 10240 B
#define O_Z     0
#define O_W     (1 * ARR)
#define STAGE   (2 * ARR)           // 20480 B
#define NSTAGE  3
#define NCHUNK  (EDIM / 32)         // 16
#define SMEM_TOTAL (NSTAGE * STAGE) // 61440 B

__global__ __launch_bounds__(256, 2) void gemm_kernel(const float* __restrict__ bias,
                                                      float* __restrict__ Y) {
    extern __shared__ char smem[];
    const uint32_t smem_base = smem_to_u32(smem);
    const int tid = threadIdx.x, wid = tid >> 5, lane = tid & 31;
    const int bx = blockIdx.x, by = blockIdx.y;

    const int row = tid >> 1, half = tid & 1;
    const size_t zbase = (size_t)(by * 128 + row) * EDIM + half * 16;
    const size_t wbase = (size_t)(bx * 128 + row) * EDIM + half * 16;
    const uint32_t sdst = smem_base + row * RSTRIDE + half * 32;

    const int wm = wid & 1, wn = wid >> 1;

    const int la_row = lane & 15;
    const int la_kh  = (lane >> 4) & 1;
    const int lb_n   = (lane & 7) + ((lane & 16) >> 1);
    const int lb_kh  = (lane >> 3) & 1;

    float acc[4][4][4];
#pragma unroll
    for (int i = 0; i < 4; i++)
#pragma unroll
        for (int j = 0; j < 4; j++)
#pragma unroll
            for (int k = 0; k < 4; k++) acc[i][j][k] = 0.f;

#define ISSUE(c, st) do { \
    uint32_t d = sdst + (st) * STAGE; \
    size_t  zo = zbase + (size_t)(c) * 32; \
    size_t  wo = wbase + (size_t)(c) * 32; \
    CP16(d + O_Z,      (const char*)(g_Zf + zo)); \
    CP16(d + O_Z + 16, (const char*)(g_Zf + zo + 8)); \
    CP16(d + O_W,      (const char*)(g_Wf + wo)); \
    CP16(d + O_W + 16, (const char*)(g_Wf + wo + 8)); \
} while (0)

    ISSUE(0, 0); CP_COMMIT();
    ISSUE(1, 1); CP_COMMIT();

    int st = 0;
    for (int c = 0; c < NCHUNK; c++) {
        if (c < NCHUNK - 1) CP_WAIT1();
        else                CP_WAIT0();
        __syncthreads();

        if (c + 2 < NCHUNK) {
            int wst = st + 2; if (wst >= NSTAGE) wst -= NSTAGE;
            ISSUE(c + 2, wst);
            CP_COMMIT();
        }

        const uint32_t sg = smem_base + st * STAGE;
        const uint32_t aZ = sg + O_Z + (wm * 64 + la_row) * RSTRIDE + la_kh * 16;
        const uint32_t bW = sg + O_W + (wn * 32 + lb_n) * RSTRIDE + lb_kh * 16;

#pragma unroll
        for (int ks = 0; ks < 2; ks++) {
            const uint32_t ko = ks * 32;
            uint32_t bw[4][2];
#pragma unroll
            for (int np = 0; np < 2; np++) {
                uint32_t t[4];
                LDSM4(t, bW + np * 16 * RSTRIDE + ko);
                bw[2*np][0] = t[0]; bw[2*np][1] = t[1];
                bw[2*np+1][0] = t[2]; bw[2*np+1][1] = t[3];
            }
#pragma unroll
            for (int mp = 0; mp < 2; mp++) {
                uint32_t az[2][4];
                LDSM4(az[0], aZ + (mp * 2 + 0) * 16 * RSTRIDE + ko);
                LDSM4(az[1], aZ + (mp * 2 + 1) * 16 * RSTRIDE + ko);
#pragma unroll
                for (int m2 = 0; m2 < 2; m2++)
#pragma unroll
                    for (int nt = 0; nt < 4; nt++)
                        MMA_F16(acc[mp*2+m2][nt], az[m2], bw[nt]);
            }
        }

        if (++st == NSTAGE) st = 0;
    }

    const int g = lane >> 2, cq = 2 * (lane & 3);
#pragma unroll
    for (int nt = 0; nt < 4; nt++) {
        const int col = bx * 128 + wn * 32 + nt * 8 + cq;
        const float2 bv = *(const float2*)(bias + col);
#pragma unroll
        for (int mt = 0; mt < 4; mt++) {
            const int r0 = by * 128 + wm * 64 + mt * 16 + g;
            float2 v0 = make_float2(acc[mt][nt][0] + bv.x, acc[mt][nt][1] + bv.y);
            float2 v1 = make_float2(acc[mt][nt][2] + bv.x, acc[mt][nt][3] + bv.y);
            *(float2*)(Y + (size_t)r0 * EDIM + col)       = v0;
            *(float2*)(Y + (size_t)(r0 + 8) * EDIM + col) = v1;
        }
    }
}

// ---------------------------------------------------------------------------
extern "C" void kernel_launch(void* const* d_in, const int* in_sizes, int n_in,
                              void* d_out, int out_size) {
    const float* x     = (const float*)d_in[0];
    const float* theta = (const float*)d_in[1];
    const float* W     = (const float*)d_in[2];
    const float* bias  = (const float*)d_in[3];
    float* out = (float*)d_out;

    cudaFuncSetAttribute(gemm_kernel, cudaFuncAttributeMaxDynamicSharedMemorySize, SMEM_TOTAL);

    qattn_kernel<<<QBLOCKS + EDIM * EDIM / 256, 256>>>(x, theta, W);
    gemm_kernel<<<dim3(EDIM / 128, NTOK / 128), 256, SMEM_TOTAL>>>(bias, out);
}

// round 10
// speedup vs baseline: 1.8801x; 1.4946x over previous
#include <cuda_runtime.h>
#include <cuda_bf16.h>
#include <cuda_fp16.h>
#include <cstdint>

#define NTOK   (8 * 2048)
#define EDIM   512
#define NHEAD  64
#define DK     8

typedef unsigned long long u64;

// Single-fp16 operands: Z (|Z|<=1) and W.
__device__ __half g_Zf[NTOK * EDIM];
__device__ __half g_Wf[EDIM * EDIM];

__device__ __forceinline__ uint32_t smem_to_u32(const void* p) {
    uint32_t a;
    asm("{ .reg .u64 t; cvta.to.shared.u64 t, %1; cvt.u32.u64 %0, t; }" : "=r"(a) : "l"(p));
    return a;
}
__device__ __forceinline__ float ex2(float x) {
    float r; asm("ex2.approx.ftz.f32 %0, %1;" : "=f"(r) : "f"(x)); return r;
}
__device__ __forceinline__ float rcp(float x) {
    float r; asm("rcp.approx.ftz.f32 %0, %1;" : "=f"(r) : "f"(x)); return r;
}
__device__ __forceinline__ uint32_t packh2(float lo, float hi) {
    uint32_t r; asm("cvt.rn.f16x2.f32 %0, %1, %2;" : "=r"(r) : "f"(hi), "f"(lo)); return r;
}

// Baseline-PTX tensor path (sm_80+)
#define CP16(dst, src) \
    asm volatile("cp.async.cg.shared.global [%0], [%1], 16;" :: "r"(dst), "l"(src))
#define CP_COMMIT()  asm volatile("cp.async.commit_group;" ::: "memory")
#define CP_WAIT1()   asm volatile("cp.async.wait_group 1;" ::: "memory")
#define CP_WAIT0()   asm volatile("cp.async.wait_group 0;" ::: "memory")

#define LDSM4(r, addr) \
    asm volatile("ldmatrix.sync.aligned.m8n8.x4.shared.b16 {%0,%1,%2,%3}, [%4];" \
        : "=r"((r)[0]), "=r"((r)[1]), "=r"((r)[2]), "=r"((r)[3]) : "r"(addr))
#define LDSM4T(r, addr) \
    asm volatile("ldmatrix.sync.aligned.m8n8.x4.trans.shared.b16 {%0,%1,%2,%3}, [%4];" \
        : "=r"((r)[0]), "=r"((r)[1]), "=r"((r)[2]), "=r"((r)[3]) : "r"(addr))

#define MMA_F16(d, a, b) \
    asm volatile("mma.sync.aligned.m16n8k16.row.col.f32.f16.f16.f32 " \
        "{%0,%1,%2,%3}, {%4,%5,%6,%7}, {%8,%9}, {%0,%1,%2,%3};" \
        : "+f"((d)[0]), "+f"((d)[1]), "+f"((d)[2]), "+f"((d)[3]) \
        : "r"((a)[0]), "r"((a)[1]), "r"((a)[2]), "r"((a)[3]), "r"((b)[0]), "r"((b)[1]))

#define MMA_F16_K8(d, a0, a1, b0) \
    asm volatile("mma.sync.aligned.m16n8k8.row.col.f32.f16.f16.f32 " \
        "{%0,%1,%2,%3}, {%4,%5}, {%6}, {%0,%1,%2,%3};" \
        : "+f"((d)[0]), "+f"((d)[1]), "+f"((d)[2]), "+f"((d)[3]) \
        : "r"(a0), "r"(a1), "r"(b0))

// ---------------------------------------------------------------------------
// Kernel A: blocks [0, QBLOCKS): projection + head-axis attention, tensor-core
//           path: S = Pn*P^T (m16n8k8), exp2 in C-frags, C-frag == A-frag of
//           m16n8k16 -> O = E*P, quad-shuffle row sums, fp16 store (permuted).
//           blocks [QBLOCKS, ...): W fp16 quantize.
// ---------------------------------------------------------------------------
#define QBLOCKS (NTOK / 8)

__global__ __launch_bounds__(256) void qattn_kernel(const float* __restrict__ x,
                                                    const float* __restrict__ theta,
                                                    const float* __restrict__ W) {
    const int tid = threadIdx.x;

    if (blockIdx.x >= QBLOCKS) {   // -------- W quantize branch --------
        int i = (blockIdx.x - QBLOCKS) * 256 + tid;
        g_Wf[i] = __float2half_rn(W[i]);
        return;
    }

    // Per-warp: Pn (scaled, A side) and P (raw, B sides), 64 rows x 8 halves.
    __shared__ __half Psm[8][2][NHEAD][DK];   // 16 KB
    __shared__ float th[DK];
    if (tid < DK) th[tid] = theta[tid];
    __syncthreads();

    const int w = tid >> 5, lane = tid & 31;
    const int token = blockIdx.x * 8 + w;
    const float* xr = x + (size_t)token * EDIM;

    float pa[8], pb[8];
    {
        float4 v0 = *(const float4*)(xr + lane * 8);
        float4 v1 = *(const float4*)(xr + lane * 8 + 4);
        pa[0] = __cosf(v0.x + th[0]); pa[1] = __cosf(v0.y + th[1]);
        pa[2] = __cosf(v0.z + th[2]); pa[3] = __cosf(v0.w + th[3]);
        pa[4] = __cosf(v1.x + th[4]); pa[5] = __cosf(v1.y + th[5]);
        pa[6] = __cosf(v1.z + th[6]); pa[7] = __cosf(v1.w + th[7]);
        float4 u0 = *(const float4*)(xr + (lane + 32) * 8);
        float4 u1 = *(const float4*)(xr + (lane + 32) * 8 + 4);
        pb[0] = __cosf(u0.x + th[0]); pb[1] = __cosf(u0.y + th[1]);
        pb[2] = __cosf(u0.z + th[2]); pb[3] = __cosf(u0.w + th[3]);
        pb[4] = __cosf(u1.x + th[4]); pb[5] = __cosf(u1.y + th[5]);
        pb[6] = __cosf(u1.z + th[6]); pb[7] = __cosf(u1.w + th[7]);
    }

    const float inv = 0.35355339059327373f * 1.4426950408889634f;  // /sqrt(8)/ln2
    {   // write scaled (A) and raw (B) fp16 copies of this lane's 2 head rows
        uint4 v;
        v.x = packh2(pa[0]*inv, pa[1]*inv); v.y = packh2(pa[2]*inv, pa[3]*inv);
        v.z = packh2(pa[4]*inv, pa[5]*inv); v.w = packh2(pa[6]*inv, pa[7]*inv);
        *(uint4*)&Psm[w][0][lane][0] = v;
        v.x = packh2(pb[0]*inv, pb[1]*inv); v.y = packh2(pb[2]*inv, pb[3]*inv);
        v.z = packh2(pb[4]*inv, pb[5]*inv); v.w = packh2(pb[6]*inv, pb[7]*inv);
        *(uint4*)&Psm[w][0][lane + 32][0] = v;
        v.x = packh2(pa[0], pa[1]); v.y = packh2(pa[2], pa[3]);
        v.z = packh2(pa[4], pa[5]); v.w = packh2(pa[6], pa[7]);
        *(uint4*)&Psm[w][1][lane][0] = v;
        v.x = packh2(pb[0], pb[1]); v.y = packh2(pb[2], pb[3]);
        v.z = packh2(pb[4], pb[5]); v.w = packh2(pb[6], pb[7]);
        *(uint4*)&Psm[w][1][lane + 32][0] = v;
    }
    __syncwarp();

    const uint32_t pnB = smem_to_u32(&Psm[w][0][0][0]);
    const uint32_t prB = smem_to_u32(&Psm[w][1][0][0]);

    // Fragments (all via ldmatrix; 32 lanes address 32 consecutive 16B rows)
    uint32_t aA[8], bS[8], bO[8];
    LDSM4 (aA,     pnB + lane * 16);          // A-frags: mt0=(0,1) mt1=(2,3)
    LDSM4 (aA + 4, pnB + 512 + lane * 16);    //          mt2=(4,5) mt3=(6,7)
    LDSM4 (bS,     prB + lane * 16);          // B-frags S: nt = reg index
    LDSM4 (bS + 4, prB + 512 + lane * 16);
    LDSM4T(bO,     prB + lane * 16);          // B-frags O: kt0=(0,1) kt1=(2,3)
    LDSM4T(bO + 4, prB + 512 + lane * 16);

    const int b = token >> 11, s = token & 2047;
    const int gID = lane >> 2, tig = lane & 3;
    __half* zb = g_Zf + (((size_t)b << 20) + (size_t)s * 8 + 2 * tig);

#pragma unroll
    for (int mt = 0; mt < 4; mt++) {
        float C[8][4];
#pragma unroll
        for (int nt = 0; nt < 8; nt++) {
            C[nt][0] = C[nt][1] = C[nt][2] = C[nt][3] = 0.f;
            MMA_F16_K8(C[nt], aA[2*mt], aA[2*mt+1], bS[nt]);
        }
        float rs0 = 0.f, rs1 = 0.f;
#pragma unroll
        for (int nt = 0; nt < 8; nt++) {
            C[nt][0] = ex2(C[nt][0]); C[nt][1] = ex2(C[nt][1]);
            C[nt][2] = ex2(C[nt][2]); C[nt][3] = ex2(C[nt][3]);
            rs0 += C[nt][0] + C[nt][1];
            rs1 += C[nt][2] + C[nt][3];
        }
        rs0 += __shfl_xor_sync(0xffffffffu, rs0, 1);
        rs0 += __shfl_xor_sync(0xffffffffu, rs0, 2);
        rs1 += __shfl_xor_sync(0xffffffffu, rs1, 1);
        rs1 += __shfl_xor_sync(0xffffffffu, rs1, 2);

        float Oc[4] = {0.f, 0.f, 0.f, 0.f};
#pragma unroll
        for (int kt = 0; kt < 4; kt++) {
            uint32_t E[4];
            E[0] = packh2(C[2*kt][0],   C[2*kt][1]);
            E[1] = packh2(C[2*kt][2],   C[2*kt][3]);
            E[2] = packh2(C[2*kt+1][0], C[2*kt+1][1]);
            E[3] = packh2(C[2*kt+1][2], C[2*kt+1][3]);
            MMA_F16(Oc, E, bO + 2*kt);
        }

        const float i0 = rcp(rs0), i1 = rcp(rs1);
        const int h0 = mt * 16 + gID;
        *(uint32_t*)(zb + ((size_t)h0 << 14))       = packh2(Oc[0]*i0, Oc[1]*i0);
        *(uint32_t*)(zb + ((size_t)(h0+8) << 14))   = packh2(Oc[2]*i1, Oc[3]*i1);
    }
}

// ---------------------------------------------------------------------------
// Kernel B: HMMA GEMM  Y[16384,512] = Z @ W^T + bias  (unchanged from R9)
// ---------------------------------------------------------------------------
#define RSTRIDE 80
#define ARR     (128 * RSTRIDE)     // 10240 B
#define O_Z     0
#define O_W     (1 * ARR)
#define STAGE   (2 * ARR)           // 20480 B
#define NSTAGE  3
#define NCHUNK  (EDIM / 32)         // 16
#define SMEM_TOTAL (NSTAGE * STAGE) // 61440 B

__global__ __launch_bounds__(256, 2) void gemm_kernel(const float* __restrict__ bias,
                                                      float* __restrict__ Y) {
    extern __shared__ char smem[];
    const uint32_t smem_base = smem_to_u32(smem);
    const int tid = threadIdx.x, wid = tid >> 5, lane = tid & 31;
    const int bx = blockIdx.x, by = blockIdx.y;

    const int row = tid >> 1, half = tid & 1;
    const size_t zbase = (size_t)(by * 128 + row) * EDIM + half * 16;
    const size_t wbase = (size_t)(bx * 128 + row) * EDIM + half * 16;
    const uint32_t sdst = smem_base + row * RSTRIDE + half * 32;

    const int wm = wid & 1, wn = wid >> 1;

    const int la_row = lane & 15;
    const int la_kh  = (lane >> 4) & 1;
    const int lb_n   = (lane & 7) + ((lane & 16) >> 1);
    const int lb_kh  = (lane >> 3) & 1;

    float acc[4][4][4];
#pragma unroll
    for (int i = 0; i < 4; i++)
#pragma unroll
        for (int j = 0; j < 4; j++)
#pragma unroll
            for (int k = 0; k < 4; k++) acc[i][j][k] = 0.f;

#define ISSUE(c, st) do { \
    uint32_t d = sdst + (st) * STAGE; \
    size_t  zo = zbase + (size_t)(c) * 32; \
    size_t  wo = wbase + (size_t)(c) * 32; \
    CP16(d + O_Z,      (const char*)(g_Zf + zo)); \
    CP16(d + O_Z + 16, (const char*)(g_Zf + zo + 8)); \
    CP16(d + O_W,      (const char*)(g_Wf + wo)); \
    CP16(d + O_W + 16, (const char*)(g_Wf + wo + 8)); \
} while (0)

    ISSUE(0, 0); CP_COMMIT();
    ISSUE(1, 1); CP_COMMIT();

    int st = 0;
    for (int c = 0; c < NCHUNK; c++) {
        if (c < NCHUNK - 1) CP_WAIT1();
        else                CP_WAIT0();
        __syncthreads();

        if (c + 2 < NCHUNK) {
            int wst = st + 2; if (wst >= NSTAGE) wst -= NSTAGE;
            ISSUE(c + 2, wst);
            CP_COMMIT();
        }

        const uint32_t sg = smem_base + st * STAGE;
        const uint32_t aZ = sg + O_Z + (wm * 64 + la_row) * RSTRIDE + la_kh * 16;
        const uint32_t bW = sg + O_W + (wn * 32 + lb_n) * RSTRIDE + lb_kh * 16;

#pragma unroll
        for (int ks = 0; ks < 2; ks++) {
            const uint32_t ko = ks * 32;
            uint32_t bw[4][2];
#pragma unroll
            for (int np = 0; np < 2; np++) {
                uint32_t t[4];
                LDSM4(t, bW + np * 16 * RSTRIDE + ko);
                bw[2*np][0] = t[0]; bw[2*np][1] = t[1];
                bw[2*np+1][0] = t[2]; bw[2*np+1][1] = t[3];
            }
#pragma unroll
            for (int mp = 0; mp < 2; mp++) {
                uint32_t az[2][4];
                LDSM4(az[0], aZ + (mp * 2 + 0) * 16 * RSTRIDE + ko);
                LDSM4(az[1], aZ + (mp * 2 + 1) * 16 * RSTRIDE + ko);
#pragma unroll
                for (int m2 = 0; m2 < 2; m2++)
#pragma unroll
                    for (int nt = 0; nt < 4; nt++)
                        MMA_F16(acc[mp*2+m2][nt], az[m2], bw[nt]);
            }
        }

        if (++st == NSTAGE) st = 0;
    }

    const int g = lane >> 2, cq = 2 * (lane & 3);
#pragma unroll
    for (int nt = 0; nt < 4; nt++) {
        const int col = bx * 128 + wn * 32 + nt * 8 + cq;
        const float2 bv = *(const float2*)(bias + col);
#pragma unroll
        for (int mt = 0; mt < 4; mt++) {
            const int r0 = by * 128 + wm * 64 + mt * 16 + g;
            float2 v0 = make_float2(acc[mt][nt][0] + bv.x, acc[mt][nt][1] + bv.y);
            float2 v1 = make_float2(acc[mt][nt][2] + bv.x, acc[mt][nt][3] + bv.y);
            *(float2*)(Y + (size_t)r0 * EDIM + col)       = v0;
            *(float2*)(Y + (size_t)(r0 + 8) * EDIM + col) = v1;
        }
    }
}

// ---------------------------------------------------------------------------
extern "C" void kernel_launch(void* const* d_in, const int* in_sizes, int n_in,
                              void* d_out, int out_size) {
    const float* x     = (const float*)d_in[0];
    const float* theta = (const float*)d_in[1];
    const float* W     = (const float*)d_in[2];
    const float* bias  = (const float*)d_in[3];
    float* out = (float*)d_out;

    cudaFuncSetAttribute(gemm_kernel, cudaFuncAttributeMaxDynamicSharedMemorySize, SMEM_TOTAL);

    qattn_kernel<<<QBLOCKS + EDIM * EDIM / 256, 256>>>(x, theta, W);
    gemm_kernel<<<dim3(EDIM / 128, NTOK / 128), 256, SMEM_TOTAL>>>(bias, out);
}